// round 11
// baseline (speedup 1.0000x reference)
#include <cuda_runtime.h>

#define BATCH 8
#define INPUT_SIZE 8192
#define HIDDEN_SIZE 8192
#define OUTPUT_SIZE 2048
#define KDIM 16384

#define TK  1024
#define TK4 (TK / 4)          // 256 float4 per batch per chunk

// Kernel-1 work decomposition: 32-row tiles x 2048-K slices
#define KSLICE 2048
#define NSPLIT1 (KDIM / KSLICE)               // 8
#define R1 4
#define ROWS_PER_BLOCK_1 (R1 * 8)             // 32
#define TILES1 (HIDDEN_SIZE / ROWS_PER_BLOCK_1)  // 256

// Scratch (allocation-free)
__device__ float g_p1[NSPLIT1][BATCH][HIDDEN_SIZE];   // 2 MB partials
__device__ float g_hidden[BATCH * HIDDEN_SIZE];       // 256 KB
__device__ float g_part[2][BATCH][OUTPUT_SIZE];       // h2o partials

// ---------------------------------------------------------------------------
__device__ __forceinline__ void cp_async16(void* smem_dst, const void* gmem_src) {
    unsigned s = (unsigned)__cvta_generic_to_shared(smem_dst);
    asm volatile("cp.async.cg.shared.global [%0], [%1], 16;\n" :: "r"(s), "l"(gmem_src));
}
__device__ __forceinline__ void cp_commit()  { asm volatile("cp.async.commit_group;\n"); }
__device__ __forceinline__ void cp_wait1()   { asm volatile("cp.async.wait_group 1;\n"); }
__device__ __forceinline__ void cp_wait0()   { asm volatile("cp.async.wait_group 0;\n"); }

// ===========================================================================
// Kernel 1: partial GEMV.  p1[s][b,row] += in[b, s*2048:(s+1)*2048]·W[row,...]
// Unit = 32 rows x 2048 K (2 chunks of 1024, double-buffered).
// grid = 256 tiles x 8 splits = 2048 blocks -> ~6.9 units per concurrent
// block slot: wave-quantization imbalance ~1%.
// ===========================================================================
__global__ __launch_bounds__(256, 2)
void rnn_i2h_kernel(const float* __restrict__ x,
                    const float* __restrict__ h0,
                    const float* __restrict__ W)      // [HIDDEN_SIZE, KDIM]
{
    __shared__ float4 s_in[2][BATCH][TK4];   // 2 x 32 KB

    const int tid   = threadIdx.x;
    const int lane  = tid & 31;
    const int warp  = tid >> 5;
    const int tile  = blockIdx.x & (TILES1 - 1);
    const int split = blockIdx.x >> 8;            // 0..7
    const int row0  = tile * ROWS_PER_BLOCK_1 + warp * R1;

    const int NCHUNK = KSLICE / TK;   // 2
    // splits 0..3 read x, 4..7 read h0 (KSLICE divides INPUT_SIZE cleanly)
    const float* in = (split < NSPLIT1 / 2)
                        ? (x  + split * KSLICE)
                        : (h0 + (split - NSPLIT1 / 2) * KSLICE);

    float acc[R1][BATCH];
    #pragma unroll
    for (int r = 0; r < R1; r++)
        #pragma unroll
        for (int b = 0; b < BATCH; b++)
            acc[r][b] = 0.0f;

    auto stage = [&](int c, int buf) {
        const float* src = in + c * TK;
        #pragma unroll
        for (int t = 0; t < 8; ++t) {       // 2048 float4 / 256 threads
            int f  = tid + t * 256;
            int b  = f >> 8;                // / TK4 (=256)
            int k4 = f & (TK4 - 1);
            cp_async16(&s_in[buf][b][k4],
                       (const float4*)(src + (size_t)b * INPUT_SIZE) + k4);
        }
        cp_commit();
    };

    stage(0, 0);

    const size_t koff = (size_t)split * KSLICE;
    const float* Wr0 = W + (size_t)(row0 + 0) * KDIM + koff;
    const float* Wr1 = W + (size_t)(row0 + 1) * KDIM + koff;
    const float* Wr2 = W + (size_t)(row0 + 2) * KDIM + koff;
    const float* Wr3 = W + (size_t)(row0 + 3) * KDIM + koff;

    for (int c = 0; c < NCHUNK; ++c) {
        const int buf = c & 1;
        __syncthreads();
        if (c + 1 < NCHUNK) { stage(c + 1, buf ^ 1); cp_wait1(); }
        else                { cp_wait0(); }
        __syncthreads();

        const float* Wc0 = Wr0 + (size_t)c * TK;
        const float* Wc1 = Wr1 + (size_t)c * TK;
        const float* Wc2 = Wr2 + (size_t)c * TK;
        const float* Wc3 = Wr3 + (size_t)c * TK;

        #pragma unroll
        for (int i = 0; i < TK4 / 32; ++i) {          // 8 strips
            const int k4 = i * 32 + lane;
            float4 w0 = __ldcs((const float4*)Wc0 + k4);
            float4 w1 = __ldcs((const float4*)Wc1 + k4);
            float4 w2 = __ldcs((const float4*)Wc2 + k4);
            float4 w3 = __ldcs((const float4*)Wc3 + k4);

            #pragma unroll
            for (int b = 0; b < BATCH; b++) {
                float4 v = s_in[buf][b][k4];
                acc[0][b] = fmaf(w0.x, v.x, acc[0][b]);
                acc[0][b] = fmaf(w0.y, v.y, acc[0][b]);
                acc[0][b] = fmaf(w0.z, v.z, acc[0][b]);
                acc[0][b] = fmaf(w0.w, v.w, acc[0][b]);
                acc[1][b] = fmaf(w1.x, v.x, acc[1][b]);
                acc[1][b] = fmaf(w1.y, v.y, acc[1][b]);
                acc[1][b] = fmaf(w1.z, v.z, acc[1][b]);
                acc[1][b] = fmaf(w1.w, v.w, acc[1][b]);
                acc[2][b] = fmaf(w2.x, v.x, acc[2][b]);
                acc[2][b] = fmaf(w2.y, v.y, acc[2][b]);
                acc[2][b] = fmaf(w2.z, v.z, acc[2][b]);
                acc[2][b] = fmaf(w2.w, v.w, acc[2][b]);
                acc[3][b] = fmaf(w3.x, v.x, acc[3][b]);
                acc[3][b] = fmaf(w3.y, v.y, acc[3][b]);
                acc[3][b] = fmaf(w3.z, v.z, acc[3][b]);
                acc[3][b] = fmaf(w3.w, v.w, acc[3][b]);
            }
        }
    }

    // warp butterfly reduction, write partial
    #pragma unroll
    for (int r = 0; r < R1; r++)
        #pragma unroll
        for (int b = 0; b < BATCH; b++)
            #pragma unroll
            for (int off = 16; off > 0; off >>= 1)
                acc[r][b] += __shfl_xor_sync(0xffffffffu, acc[r][b], off);

    #pragma unroll
    for (int r = 0; r < R1; r++) {
        const int row = row0 + r;
        #pragma unroll
        for (int b = 0; b < BATCH; b++)
            if (lane == b)
                g_p1[split][b][row] = acc[r][b];
    }
}

// ===========================================================================
// Reduce 1: hidden = tanh(sum_8 p1 + bias1)   (float4)
// ===========================================================================
__global__ void rnn_reduce1_kernel(const float* __restrict__ bias)
{
    int idx = blockIdx.x * 256 + threadIdx.x;     // 16384 float4s
    int b  = idx >> 11;                            // / (HIDDEN/4)
    int h4 = idx & (HIDDEN_SIZE / 4 - 1);
    float4 a = __ldg((const float4*)bias + h4);
    #pragma unroll
    for (int s = 0; s < NSPLIT1; s++) {
        float4 p = ((const float4*)&g_p1[s][b][0])[h4];
        a.x += p.x; a.y += p.y; a.z += p.z; a.w += p.w;
    }
    float4 r = make_float4(tanhf(a.x), tanhf(a.y), tanhf(a.z), tanhf(a.w));
    ((float4*)(g_hidden + b * HIDDEN_SIZE))[h4] = r;
}

// ===========================================================================
// Kernel 2: K-split GEMV (unchanged from R10). 16 rows/block, 2 halves.
// ===========================================================================
#define R2 2
#define ROWS_PER_BLOCK_2 (R2 * 8)   // 16
#define KSPLIT 2
#define KHALF (HIDDEN_SIZE / KSPLIT)   // 4096

__global__ __launch_bounds__(256, 2)
void rnn_h2o_kernel(const float* __restrict__ W2)   // [OUTPUT_SIZE, HIDDEN_SIZE]
{
    __shared__ float4 s_in[2][BATCH][TK4];   // 2 x 32 KB

    const int tid  = threadIdx.x;
    const int lane = tid & 31;
    const int warp = tid >> 5;
    const int tile = blockIdx.x & 127;
    const int half = blockIdx.x >> 7;
    const int row0 = tile * ROWS_PER_BLOCK_2 + warp * R2;
    const int kbase = half * KHALF;

    const int NCHUNK = KHALF / TK;   // 4

    float acc[R2][BATCH];
    #pragma unroll
    for (int r = 0; r < R2; r++)
        #pragma unroll
        for (int b = 0; b < BATCH; b++)
            acc[r][b] = 0.0f;

    auto stage = [&](int c, int buf) {
        const float* src = g_hidden + kbase + c * TK;
        #pragma unroll
        for (int t = 0; t < 8; ++t) {
            int f  = tid + t * 256;
            int b  = f >> 8;
            int k4 = f & (TK4 - 1);
            cp_async16(&s_in[buf][b][k4],
                       (const float4*)(src + (size_t)b * HIDDEN_SIZE) + k4);
        }
        cp_commit();
    };

    stage(0, 0);

    const float* W0 = W2 + (size_t)(row0 + 0) * HIDDEN_SIZE + kbase;
    const float* W1 = W2 + (size_t)(row0 + 1) * HIDDEN_SIZE + kbase;

    for (int c = 0; c < NCHUNK; ++c) {
        const int buf = c & 1;
        __syncthreads();
        if (c + 1 < NCHUNK) { stage(c + 1, buf ^ 1); cp_wait1(); }
        else                { cp_wait0(); }
        __syncthreads();

        const float* Wc0 = W0 + (size_t)c * TK;
        const float* Wc1 = W1 + (size_t)c * TK;

        #pragma unroll
        for (int i = 0; i < TK4 / 32; ++i) {          // 8 strips
            const int k4 = i * 32 + lane;
            float4 w0 = __ldcs((const float4*)Wc0 + k4);
            float4 w1 = __ldcs((const float4*)Wc1 + k4);

            #pragma unroll
            for (int b = 0; b < BATCH; b++) {
                float4 v = s_in[buf][b][k4];
                acc[0][b] = fmaf(w0.x, v.x, acc[0][b]);
                acc[0][b] = fmaf(w0.y, v.y, acc[0][b]);
                acc[0][b] = fmaf(w0.z, v.z, acc[0][b]);
                acc[0][b] = fmaf(w0.w, v.w, acc[0][b]);
                acc[1][b] = fmaf(w1.x, v.x, acc[1][b]);
                acc[1][b] = fmaf(w1.y, v.y, acc[1][b]);
                acc[1][b] = fmaf(w1.z, v.z, acc[1][b]);
                acc[1][b] = fmaf(w1.w, v.w, acc[1][b]);
            }
        }
    }

    #pragma unroll
    for (int r = 0; r < R2; r++)
        #pragma unroll
        for (int b = 0; b < BATCH; b++)
            #pragma unroll
            for (int off = 16; off > 0; off >>= 1)
                acc[r][b] += __shfl_xor_sync(0xffffffffu, acc[r][b], off);

    #pragma unroll
    for (int r = 0; r < R2; r++) {
        const int row = row0 + r;
        #pragma unroll
        for (int b = 0; b < BATCH; b++)
            if (lane == b)
                g_part[half][b][row] = acc[r][b];
    }
}

// ===========================================================================
// Reduce 2: out = part[0] + part[1] + bias2
// ===========================================================================
__global__ void rnn_reduce_kernel(const float* __restrict__ bias2,
                                  float* __restrict__ out)
{
    int idx = blockIdx.x * blockDim.x + threadIdx.x;   // 16384
    int b = idx >> 11;
    int o = idx & (OUTPUT_SIZE - 1);
    out[idx] = g_part[0][b][o] + g_part[1][b][o] + __ldg(bias2 + o);
}

// ---------------------------------------------------------------------------
// Inputs: x, initial_hidden, i2h_weight, i2h_bias, h2o_weight, h2o_bias
// ---------------------------------------------------------------------------
extern "C" void kernel_launch(void* const* d_in, const int* in_sizes, int n_in,
                              void* d_out, int out_size) {
    const float* x    = (const float*)d_in[0];
    const float* h0   = (const float*)d_in[1];
    const float* W1   = (const float*)d_in[2];
    const float* b1   = (const float*)d_in[3];
    const float* W2   = (const float*)d_in[4];
    const float* b2   = (const float*)d_in[5];
    float* out        = (float*)d_out;

    rnn_i2h_kernel<<<TILES1 * NSPLIT1, 256>>>(x, h0, W1);
    rnn_reduce1_kernel<<<(BATCH * HIDDEN_SIZE / 4) / 256, 256>>>(b1);
    rnn_h2o_kernel<<<(OUTPUT_SIZE / ROWS_PER_BLOCK_2) * KSPLIT, 256>>>(W2);
    rnn_reduce_kernel<<<(BATCH * OUTPUT_SIZE) / 256, 256>>>(b2, out);
}

// round 12
// speedup vs baseline: 1.0342x; 1.0342x over previous
#include <cuda_runtime.h>

#define BATCH 8
#define INPUT_SIZE 8192
#define HIDDEN_SIZE 8192
#define OUTPUT_SIZE 2048
#define KDIM 16384

// ---- Kernel 1 decomposition: 8 K-slices x 37 persistent blocks ------------
#define NSLICE1 8
#define KSLICE1 (KDIM / NSLICE1)        // 2048
#define KS1_F4  (KSLICE1 / 4)           // 512 float4 per batch
#define BLKS_PER_SLICE1 37              // 8*37 = 296 = 2*148 SMs
#define R1 4
#define TILE_ROWS_1 (R1 * 8)            // 32
#define NTILES1 (HIDDEN_SIZE / TILE_ROWS_1)   // 256

// ---- Kernel 2 decomposition: 8 K-slices x 37 persistent blocks ------------
#define NSLICE2 8
#define KSLICE2 (HIDDEN_SIZE / NSLICE2) // 1024
#define KS2_F4  (KSLICE2 / 4)           // 256 float4 per batch
#define BLKS_PER_SLICE2 37
#define TILE_ROWS_2 8                   // 1 row per warp
#define NTILES2 (OUTPUT_SIZE / TILE_ROWS_2)   // 256

// Scratch (allocation-free)
__device__ float g_p1[NSLICE1][BATCH][HIDDEN_SIZE];   // 2 MB
__device__ float g_hidden[BATCH][HIDDEN_SIZE];        // 256 KB
__device__ float g_p2[NSLICE2][BATCH][OUTPUT_SIZE];   // 512 KB

// ===========================================================================
// Kernel 1: persistent slice-resident partial GEMV.
//   p1[s][b,row] = in_s[b,:] · W[row, s*2048:(s+1)*2048]
// grid = 296 (8 slices x 37). Stage the 64 KB input slice ONCE, then sweep
// ~7 row tiles of 32 rows with barrier-free weight streaming (R10 inner loop).
// ===========================================================================
__global__ __launch_bounds__(256, 2)
void rnn_i2h_kernel(const float* __restrict__ x,
                    const float* __restrict__ h0,
                    const float* __restrict__ W)      // [HIDDEN_SIZE, KDIM]
{
    extern __shared__ float4 s_in[];                  // [BATCH][KS1_F4] = 64 KB

    const int tid   = threadIdx.x;
    const int lane  = tid & 31;
    const int warp  = tid >> 5;
    const int slice = blockIdx.x / BLKS_PER_SLICE1;   // 0..7
    const int local = blockIdx.x % BLKS_PER_SLICE1;   // 0..36

    // ---- stage input slice once: 8 x 2048 floats = 4096 float4 -----------
    const float* in = (slice < NSLICE1 / 2)
                        ? (x  + slice * KSLICE1)
                        : (h0 + slice * KSLICE1 - INPUT_SIZE);
    #pragma unroll
    for (int t = 0; t < 16; ++t) {
        int f  = tid + t * 256;
        int b  = f >> 9;                   // / KS1_F4 (=512)
        int k4 = f & (KS1_F4 - 1);
        s_in[b * KS1_F4 + k4] =
            ((const float4*)(in + (size_t)b * INPUT_SIZE))[k4];
    }
    __syncthreads();        // the ONLY barrier in this kernel

    const size_t koff = (size_t)slice * KSLICE1;

    // ---- sweep row tiles: local, local+37, ... (6 or 7 tiles) -------------
    for (int tile = local; tile < NTILES1; tile += BLKS_PER_SLICE1) {
        const int row0 = tile * TILE_ROWS_1 + warp * R1;

        float acc[R1][BATCH];
        #pragma unroll
        for (int r = 0; r < R1; r++)
            #pragma unroll
            for (int b = 0; b < BATCH; b++)
                acc[r][b] = 0.0f;

        const float* Wc0 = W + (size_t)(row0 + 0) * KDIM + koff;
        const float* Wc1 = W + (size_t)(row0 + 1) * KDIM + koff;
        const float* Wc2 = W + (size_t)(row0 + 2) * KDIM + koff;
        const float* Wc3 = W + (size_t)(row0 + 3) * KDIM + koff;

        #pragma unroll
        for (int i = 0; i < KS1_F4 / 32; ++i) {       // 16 strips
            const int k4 = i * 32 + lane;
            float4 w0 = __ldcs((const float4*)Wc0 + k4);
            float4 w1 = __ldcs((const float4*)Wc1 + k4);
            float4 w2 = __ldcs((const float4*)Wc2 + k4);
            float4 w3 = __ldcs((const float4*)Wc3 + k4);

            #pragma unroll
            for (int b = 0; b < BATCH; b++) {
                float4 v = s_in[b * KS1_F4 + k4];
                acc[0][b] = fmaf(w0.x, v.x, acc[0][b]);
                acc[0][b] = fmaf(w0.y, v.y, acc[0][b]);
                acc[0][b] = fmaf(w0.z, v.z, acc[0][b]);
                acc[0][b] = fmaf(w0.w, v.w, acc[0][b]);
                acc[1][b] = fmaf(w1.x, v.x, acc[1][b]);
                acc[1][b] = fmaf(w1.y, v.y, acc[1][b]);
                acc[1][b] = fmaf(w1.z, v.z, acc[1][b]);
                acc[1][b] = fmaf(w1.w, v.w, acc[1][b]);
                acc[2][b] = fmaf(w2.x, v.x, acc[2][b]);
                acc[2][b] = fmaf(w2.y, v.y, acc[2][b]);
                acc[2][b] = fmaf(w2.z, v.z, acc[2][b]);
                acc[2][b] = fmaf(w2.w, v.w, acc[2][b]);
                acc[3][b] = fmaf(w3.x, v.x, acc[3][b]);
                acc[3][b] = fmaf(w3.y, v.y, acc[3][b]);
                acc[3][b] = fmaf(w3.z, v.z, acc[3][b]);
                acc[3][b] = fmaf(w3.w, v.w, acc[3][b]);
            }
        }

        // warp butterfly reduction, write partials
        #pragma unroll
        for (int r = 0; r < R1; r++)
            #pragma unroll
            for (int b = 0; b < BATCH; b++)
                #pragma unroll
                for (int off = 16; off > 0; off >>= 1)
                    acc[r][b] += __shfl_xor_sync(0xffffffffu, acc[r][b], off);

        #pragma unroll
        for (int r = 0; r < R1; r++) {
            const int row = row0 + r;
            #pragma unroll
            for (int b = 0; b < BATCH; b++)
                if (lane == b)
                    g_p1[slice][b][row] = acc[r][b];
        }
    }
}

// ===========================================================================
// Reduce 1: hidden = tanh(sum_8 p1 + bias1)   (float4)
// ===========================================================================
__global__ void rnn_reduce1_kernel(const float* __restrict__ bias)
{
    int idx = blockIdx.x * 256 + threadIdx.x;     // 16384 float4s
    int b  = idx >> 11;                            // / (HIDDEN/4)
    int h4 = idx & (HIDDEN_SIZE / 4 - 1);
    float4 a = __ldg((const float4*)bias + h4);
    #pragma unroll
    for (int s = 0; s < NSLICE1; s++) {
        float4 p = ((const float4*)&g_p1[s][b][0])[h4];
        a.x += p.x; a.y += p.y; a.z += p.z; a.w += p.w;
    }
    float4 r = make_float4(tanhf(a.x), tanhf(a.y), tanhf(a.z), tanhf(a.w));
    ((float4*)&g_hidden[b][0])[h4] = r;
}

// ===========================================================================
// Kernel 2: persistent slice-resident h2o partial GEMV.
//   p2[s][b,row] = hidden[b, s*1024:(s+1)*1024] · W2[row, ...]
// grid = 296 (8 slices x 37); 8-row tiles, 1 row/warp; stage 32 KB once.
// ===========================================================================
__global__ __launch_bounds__(256, 2)
void rnn_h2o_kernel(const float* __restrict__ W2)   // [OUT, HIDDEN]
{
    __shared__ float4 s_in[BATCH][KS2_F4];          // 32 KB

    const int tid   = threadIdx.x;
    const int lane  = tid & 31;
    const int warp  = tid >> 5;
    const int slice = blockIdx.x / BLKS_PER_SLICE2;
    const int local = blockIdx.x % BLKS_PER_SLICE2;
    const int kbase = slice * KSLICE2;

    // ---- stage slice once: 8 x 1024 floats = 2048 float4 ------------------
    #pragma unroll
    for (int t = 0; t < 8; ++t) {
        int f  = tid + t * 256;
        int b  = f >> 8;                   // / KS2_F4 (=256)
        int k4 = f & (KS2_F4 - 1);
        s_in[b][k4] = ((const float4*)&g_hidden[b][kbase])[k4];
    }
    __syncthreads();        // only barrier

    for (int tile = local; tile < NTILES2; tile += BLKS_PER_SLICE2) {
        const int row = tile * TILE_ROWS_2 + warp;

        float acc[BATCH];
        #pragma unroll
        for (int b = 0; b < BATCH; b++) acc[b] = 0.0f;

        const float* Wr = W2 + (size_t)row * HIDDEN_SIZE + kbase;

        #pragma unroll
        for (int i = 0; i < KS2_F4 / 32; ++i) {       // 8 strips
            const int k4 = i * 32 + lane;
            float4 w = __ldcs((const float4*)Wr + k4);
            #pragma unroll
            for (int b = 0; b < BATCH; b++) {
                float4 v = s_in[b][k4];
                acc[b] = fmaf(w.x, v.x, acc[b]);
                acc[b] = fmaf(w.y, v.y, acc[b]);
                acc[b] = fmaf(w.z, v.z, acc[b]);
                acc[b] = fmaf(w.w, v.w, acc[b]);
            }
        }

        #pragma unroll
        for (int b = 0; b < BATCH; b++)
            #pragma unroll
            for (int off = 16; off > 0; off >>= 1)
                acc[b] += __shfl_xor_sync(0xffffffffu, acc[b], off);

        #pragma unroll
        for (int b = 0; b < BATCH; b++)
            if (lane == b)
                g_p2[slice][b][row] = acc[b];
    }
}

// ===========================================================================
// Reduce 2: out = sum_8 p2 + bias2   (float4)
// ===========================================================================
__global__ void rnn_reduce2_kernel(const float* __restrict__ bias2,
                                   float* __restrict__ out)
{
    int idx = blockIdx.x * 256 + threadIdx.x;     // 4096 float4s
    int b  = idx >> 9;                             // / (OUT/4)
    int o4 = idx & (OUTPUT_SIZE / 4 - 1);
    float4 a = __ldg((const float4*)bias2 + o4);
    #pragma unroll
    for (int s = 0; s < NSLICE2; s++) {
        float4 p = ((const float4*)&g_p2[s][b][0])[o4];
        a.x += p.x; a.y += p.y; a.z += p.z; a.w += p.w;
    }
    ((float4*)out)[idx] = a;
}

// ---------------------------------------------------------------------------
// Inputs: x, initial_hidden, i2h_weight, i2h_bias, h2o_weight, h2o_bias
// ---------------------------------------------------------------------------
extern "C" void kernel_launch(void* const* d_in, const int* in_sizes, int n_in,
                              void* d_out, int out_size) {
    const float* x  = (const float*)d_in[0];
    const float* h0 = (const float*)d_in[1];
    const float* W1 = (const float*)d_in[2];
    const float* b1 = (const float*)d_in[3];
    const float* W2 = (const float*)d_in[4];
    const float* b2 = (const float*)d_in[5];
    float* out      = (float*)d_out;

    const int SMEM1 = BATCH * KS1_F4 * sizeof(float4);   // 64 KB dynamic
    cudaFuncSetAttribute(rnn_i2h_kernel,
                         cudaFuncAttributeMaxDynamicSharedMemorySize, SMEM1);

    rnn_i2h_kernel<<<NSLICE1 * BLKS_PER_SLICE1, 256, SMEM1>>>(x, h0, W1);
    rnn_reduce1_kernel<<<(BATCH * HIDDEN_SIZE / 4) / 256, 256>>>(b1);
    rnn_h2o_kernel<<<NSLICE2 * BLKS_PER_SLICE2, 256>>>(W2);
    rnn_reduce2_kernel<<<(BATCH * OUTPUT_SIZE / 4) / 256, 256>>>(b2, out);
}

// round 13
// speedup vs baseline: 1.0923x; 1.0561x over previous
#include <cuda_runtime.h>

#define BATCH 8
#define INPUT_SIZE 8192
#define HIDDEN_SIZE 8192
#define OUTPUT_SIZE 2048
#define KDIM 16384

typedef unsigned long long u64;

// Intermediate hidden activations (8 x 8192 fp32 = 256 KB).
__device__ float g_hidden[BATCH * HIDDEN_SIZE];
// Partial sums for the K-split h2o GEMV: [split][batch][out]
__device__ float g_part[2][BATCH][OUTPUT_SIZE];

// ---------------------------------------------------------------------------
// cp.async helpers (16B variant)
// ---------------------------------------------------------------------------
__device__ __forceinline__ void cp_async16(void* smem_dst, const void* gmem_src) {
    unsigned s = (unsigned)__cvta_generic_to_shared(smem_dst);
    asm volatile("cp.async.cg.shared.global [%0], [%1], 16;\n" :: "r"(s), "l"(gmem_src));
}
__device__ __forceinline__ void cp_commit()  { asm volatile("cp.async.commit_group;\n"); }
__device__ __forceinline__ void cp_wait1()   { asm volatile("cp.async.wait_group 1;\n"); }
__device__ __forceinline__ void cp_wait0()   { asm volatile("cp.async.wait_group 0;\n"); }

// Packed dual-FMA (non-volatile, pure, reorderable): d += a*b elementwise on
// two packed f32. Operands come straight from LDG.128 / LDS.128 register
// pairs (ulonglong2.x/.y) — no packing movs anywhere.
__device__ __forceinline__ void fma2(u64& d, u64 a, u64 b) {
    asm("fma.rn.f32x2 %0, %1, %2, %0;" : "+l"(d) : "l"(a), "l"(b));
}
__device__ __forceinline__ float pair_sum(u64 v) {
    return __uint_as_float((unsigned)v) + __uint_as_float((unsigned)(v >> 32));
}

#define TK  1024
#define TK4 (TK / 4)    // 256 16-byte elements per batch per chunk

// ===========================================================================
// Kernel 1: hidden[b,h] = tanh( x[b,:]·W[h,0:8192] + h0[b,:]·W[h,8192:] + b1[h] )
// 256 threads (8 warps), 4 rows/warp -> 32 rows/block, grid = 256.
// R10 structure (TK=1024 double-buffered cp.async staging) with the inner
// loop on FFMA2: weights and inputs consumed as native ulonglong2 (the
// LDG.128/LDS.128 register pairs ARE the f32x2 operands).
// ===========================================================================
#define R1 4
#define ROWS_PER_BLOCK_1 (R1 * 8)   // 32

__global__ __launch_bounds__(256, 2)
void rnn_i2h_kernel(const float* __restrict__ x,
                    const float* __restrict__ h0,
                    const float* __restrict__ W,      // [HIDDEN_SIZE, KDIM]
                    const float* __restrict__ bias)
{
    __shared__ ulonglong2 s_in[2][BATCH][TK4];   // 2 x 32 KB

    const int tid  = threadIdx.x;
    const int lane = tid & 31;
    const int warp = tid >> 5;
    const int row0 = blockIdx.x * ROWS_PER_BLOCK_1 + warp * R1;

    const int NCHUNK = KDIM / TK;          // 16
    const int XCHUNK = INPUT_SIZE / TK;    // 8

    u64 acc[R1][BATCH];
    #pragma unroll
    for (int r = 0; r < R1; r++)
        #pragma unroll
        for (int b = 0; b < BATCH; b++)
            acc[r][b] = 0ull;              // two packed +0.0f

    auto stage = [&](int c, int buf) {
        const float* src = (c < XCHUNK) ? (x + c * TK)
                                        : (h0 + (c - XCHUNK) * TK);
        #pragma unroll
        for (int t = 0; t < 8; ++t) {       // 2048 x 16B / 256 threads
            int f  = tid + t * 256;
            int b  = f >> 8;                // / TK4 (=256)
            int k4 = f & (TK4 - 1);
            cp_async16(&s_in[buf][b][k4],
                       (const float4*)(src + (size_t)b * INPUT_SIZE) + k4);
        }
        cp_commit();
    };

    stage(0, 0);

    const ulonglong2* Wr0 = (const ulonglong2*)(W + (size_t)(row0 + 0) * KDIM);
    const ulonglong2* Wr1 = (const ulonglong2*)(W + (size_t)(row0 + 1) * KDIM);
    const ulonglong2* Wr2 = (const ulonglong2*)(W + (size_t)(row0 + 2) * KDIM);
    const ulonglong2* Wr3 = (const ulonglong2*)(W + (size_t)(row0 + 3) * KDIM);

    for (int c = 0; c < NCHUNK; ++c) {
        const int buf = c & 1;
        __syncthreads();                     // buffer (c+1)&1 is free now
        if (c + 1 < NCHUNK) { stage(c + 1, buf ^ 1); cp_wait1(); }
        else                { cp_wait0(); }
        __syncthreads();                     // chunk c visible to all warps

        const ulonglong2* Wc0 = Wr0 + c * TK4;
        const ulonglong2* Wc1 = Wr1 + c * TK4;
        const ulonglong2* Wc2 = Wr2 + c * TK4;
        const ulonglong2* Wc3 = Wr3 + c * TK4;

        #pragma unroll
        for (int i = 0; i < TK4 / 32; ++i) {          // 8 strips
            const int k4 = i * 32 + lane;
            ulonglong2 w0 = __ldcs(Wc0 + k4);
            ulonglong2 w1 = __ldcs(Wc1 + k4);
            ulonglong2 w2 = __ldcs(Wc2 + k4);
            ulonglong2 w3 = __ldcs(Wc3 + k4);

            #pragma unroll
            for (int b = 0; b < BATCH; b++) {
                ulonglong2 v = s_in[buf][b][k4];
                fma2(acc[0][b], w0.x, v.x);
                fma2(acc[0][b], w0.y, v.y);
                fma2(acc[1][b], w1.x, v.x);
                fma2(acc[1][b], w1.y, v.y);
                fma2(acc[2][b], w2.x, v.x);
                fma2(acc[2][b], w2.y, v.y);
                fma2(acc[3][b], w3.x, v.x);
                fma2(acc[3][b], w3.y, v.y);
            }
        }
    }

    // pair-sum then warp butterfly reduction
    #pragma unroll
    for (int r = 0; r < R1; r++) {
        #pragma unroll
        for (int b = 0; b < BATCH; b++) {
            float s = pair_sum(acc[r][b]);
            #pragma unroll
            for (int off = 16; off > 0; off >>= 1)
                s += __shfl_xor_sync(0xffffffffu, s, off);
            if (lane == b) {
                const int row = row0 + r;
                g_hidden[b * HIDDEN_SIZE + row] = tanhf(s + __ldg(bias + row));
            }
        }
    }
}

// ===========================================================================
// Kernel 2: K-split GEMV (unchanged from R10). 16 rows/block, 2 halves.
// ===========================================================================
#define R2 2
#define ROWS_PER_BLOCK_2 (R2 * 8)   // 16
#define KSPLIT 2
#define KHALF (HIDDEN_SIZE / KSPLIT)   // 4096

__global__ __launch_bounds__(256, 2)
void rnn_h2o_kernel(const float* __restrict__ W2)   // [OUTPUT_SIZE, HIDDEN_SIZE]
{
    __shared__ float4 s_in[2][BATCH][TK4];   // 2 x 32 KB

    const int tid  = threadIdx.x;
    const int lane = tid & 31;
    const int warp = tid >> 5;
    const int tile = blockIdx.x & 127;          // 128 row tiles
    const int half = blockIdx.x >> 7;           // 0 or 1
    const int row0 = tile * ROWS_PER_BLOCK_2 + warp * R2;
    const int kbase = half * KHALF;

    const int NCHUNK = KHALF / TK;   // 4

    float acc[R2][BATCH];
    #pragma unroll
    for (int r = 0; r < R2; r++)
        #pragma unroll
        for (int b = 0; b < BATCH; b++)
            acc[r][b] = 0.0f;

    auto stage = [&](int c, int buf) {
        const float* src = g_hidden + kbase + c * TK;
        #pragma unroll
        for (int t = 0; t < 8; ++t) {
            int f  = tid + t * 256;
            int b  = f >> 8;
            int k4 = f & (TK4 - 1);
            cp_async16(&s_in[buf][b][k4],
                       (const float4*)(src + (size_t)b * HIDDEN_SIZE) + k4);
        }
        cp_commit();
    };

    stage(0, 0);

    const float* W0 = W2 + (size_t)(row0 + 0) * HIDDEN_SIZE + kbase;
    const float* W1 = W2 + (size_t)(row0 + 1) * HIDDEN_SIZE + kbase;

    for (int c = 0; c < NCHUNK; ++c) {
        const int buf = c & 1;
        __syncthreads();
        if (c + 1 < NCHUNK) { stage(c + 1, buf ^ 1); cp_wait1(); }
        else                { cp_wait0(); }
        __syncthreads();

        const float* Wc0 = W0 + (size_t)c * TK;
        const float* Wc1 = W1 + (size_t)c * TK;

        #pragma unroll
        for (int i = 0; i < TK4 / 32; ++i) {          // 8 strips
            const int k4 = i * 32 + lane;
            float4 w0 = __ldcs((const float4*)Wc0 + k4);
            float4 w1 = __ldcs((const float4*)Wc1 + k4);

            #pragma unroll
            for (int b = 0; b < BATCH; b++) {
                float4 v = s_in[buf][b][k4];
                acc[0][b] = fmaf(w0.x, v.x, acc[0][b]);
                acc[0][b] = fmaf(w0.y, v.y, acc[0][b]);
                acc[0][b] = fmaf(w0.z, v.z, acc[0][b]);
                acc[0][b] = fmaf(w0.w, v.w, acc[0][b]);
                acc[1][b] = fmaf(w1.x, v.x, acc[1][b]);
                acc[1][b] = fmaf(w1.y, v.y, acc[1][b]);
                acc[1][b] = fmaf(w1.z, v.z, acc[1][b]);
                acc[1][b] = fmaf(w1.w, v.w, acc[1][b]);
            }
        }
    }

    #pragma unroll
    for (int r = 0; r < R2; r++)
        #pragma unroll
        for (int b = 0; b < BATCH; b++)
            #pragma unroll
            for (int off = 16; off > 0; off >>= 1)
                acc[r][b] += __shfl_xor_sync(0xffffffffu, acc[r][b], off);

    #pragma unroll
    for (int r = 0; r < R2; r++) {
        const int row = row0 + r;
        #pragma unroll
        for (int b = 0; b < BATCH; b++)
            if (lane == b)
                g_part[half][b][row] = acc[r][b];
    }
}

// ===========================================================================
// Kernel 3: out[b,o] = part[0][b,o] + part[1][b,o] + bias2[o]
// ===========================================================================
__global__ void rnn_reduce_kernel(const float* __restrict__ bias2,
                                  float* __restrict__ out)
{
    int idx = blockIdx.x * blockDim.x + threadIdx.x;   // 16384 total
    int b = idx >> 11;               // / OUTPUT_SIZE
    int o = idx & (OUTPUT_SIZE - 1);
    out[idx] = g_part[0][b][o] + g_part[1][b][o] + __ldg(bias2 + o);
}

// ---------------------------------------------------------------------------
// Inputs: x, initial_hidden, i2h_weight, i2h_bias, h2o_weight, h2o_bias
// ---------------------------------------------------------------------------
extern "C" void kernel_launch(void* const* d_in, const int* in_sizes, int n_in,
                              void* d_out, int out_size) {
    const float* x    = (const float*)d_in[0];
    const float* h0   = (const float*)d_in[1];
    const float* W1   = (const float*)d_in[2];
    const float* b1   = (const float*)d_in[3];
    const float* W2   = (const float*)d_in[4];
    const float* b2   = (const float*)d_in[5];
    float* out        = (float*)d_out;

    rnn_i2h_kernel<<<HIDDEN_SIZE / ROWS_PER_BLOCK_1, 256>>>(x, h0, W1, b1);
    rnn_h2o_kernel<<<(OUTPUT_SIZE / ROWS_PER_BLOCK_2) * KSPLIT, 256>>>(W2);
    rnn_reduce_kernel<<<(BATCH * OUTPUT_SIZE) / 256, 256>>>(b2, out);
}

// round 14
// speedup vs baseline: 1.1391x; 1.0428x over previous
#include <cuda_runtime.h>

#define BATCH 8
#define INPUT_SIZE 8192
#define HIDDEN_SIZE 8192
#define OUTPUT_SIZE 2048
#define KDIM 16384

typedef unsigned long long u64;

// ---- Kernel 1: 8 K-slices x 37 persistent blocks = 296 = 2 x 148 SMs ------
#define NSLICE1 8
#define KSLICE1 (KDIM / NSLICE1)        // 2048
#define KS1_16B (KSLICE1 / 4)           // 512 x 16B per batch
#define BLKS_PER_SLICE1 37
#define R1 4
#define TILE_ROWS_1 (R1 * 8)            // 32
#define NTILES1 (HIDDEN_SIZE / TILE_ROWS_1)   // 256

// Scratch (allocation-free)
__device__ float g_p1[NSLICE1][BATCH][HIDDEN_SIZE];   // 2 MB
__device__ float g_hidden[BATCH * HIDDEN_SIZE];       // 256 KB
__device__ float g_part[2][BATCH][OUTPUT_SIZE];       // h2o partials

// ---------------------------------------------------------------------------
__device__ __forceinline__ void cp_async16(void* smem_dst, const void* gmem_src) {
    unsigned s = (unsigned)__cvta_generic_to_shared(smem_dst);
    asm volatile("cp.async.cg.shared.global [%0], [%1], 16;\n" :: "r"(s), "l"(gmem_src));
}
__device__ __forceinline__ void cp_commit()  { asm volatile("cp.async.commit_group;\n"); }
__device__ __forceinline__ void cp_wait1()   { asm volatile("cp.async.wait_group 1;\n"); }
__device__ __forceinline__ void cp_wait0()   { asm volatile("cp.async.wait_group 0;\n"); }

// Packed dual-FMA (non-volatile, reorderable). Operands are native
// ulonglong2 halves from LDG.128/LDS.128 — zero packing cost.
__device__ __forceinline__ void fma2(u64& d, u64 a, u64 b) {
    asm("fma.rn.f32x2 %0, %1, %2, %0;" : "+l"(d) : "l"(a), "l"(b));
}
__device__ __forceinline__ float pair_sum(u64 v) {
    return __uint_as_float((unsigned)v) + __uint_as_float((unsigned)(v >> 32));
}

// ===========================================================================
// Kernel 1: persistent slice-resident partial GEMV (FFMA2 inner loop).
//   p1[s][b,row] = in_s[b,:] · W[row, s*2048:(s+1)*2048]
// grid = 296: every SM gets exactly 2 blocks -> zero wave quantization.
// Stage the 64 KB input slice ONCE (one barrier), sweep ~7 row tiles with
// barrier-free FFMA2 weight streaming.
// ===========================================================================
__global__ __launch_bounds__(256, 2)
void rnn_i2h_kernel(const float* __restrict__ x,
                    const float* __restrict__ h0,
                    const float* __restrict__ W)      // [HIDDEN_SIZE, KDIM]
{
    extern __shared__ ulonglong2 s_in[];              // [BATCH][KS1_16B] 64 KB

    const int tid   = threadIdx.x;
    const int lane  = tid & 31;
    const int warp  = tid >> 5;
    const int slice = blockIdx.x / BLKS_PER_SLICE1;   // 0..7
    const int local = blockIdx.x % BLKS_PER_SLICE1;   // 0..36

    // ---- stage input slice once: 8 x 2048 floats = 4096 x 16B -------------
    const float* in = (slice < NSLICE1 / 2)
                        ? (x  + slice * KSLICE1)
                        : (h0 + slice * KSLICE1 - INPUT_SIZE);
    #pragma unroll
    for (int t = 0; t < 16; ++t) {
        int f  = tid + t * 256;
        int b  = f >> 9;                   // / KS1_16B (=512)
        int k4 = f & (KS1_16B - 1);
        s_in[b * KS1_16B + k4] =
            ((const ulonglong2*)(in + (size_t)b * INPUT_SIZE))[k4];
    }
    __syncthreads();        // the ONLY barrier

    const size_t koff = (size_t)slice * KSLICE1;

    for (int tile = local; tile < NTILES1; tile += BLKS_PER_SLICE1) {
        const int row0 = tile * TILE_ROWS_1 + warp * R1;

        u64 acc[R1][BATCH];
        #pragma unroll
        for (int r = 0; r < R1; r++)
            #pragma unroll
            for (int b = 0; b < BATCH; b++)
                acc[r][b] = 0ull;

        const ulonglong2* Wc0 = (const ulonglong2*)(W + (size_t)(row0 + 0) * KDIM + koff);
        const ulonglong2* Wc1 = (const ulonglong2*)(W + (size_t)(row0 + 1) * KDIM + koff);
        const ulonglong2* Wc2 = (const ulonglong2*)(W + (size_t)(row0 + 2) * KDIM + koff);
        const ulonglong2* Wc3 = (const ulonglong2*)(W + (size_t)(row0 + 3) * KDIM + koff);

        #pragma unroll
        for (int i = 0; i < KS1_16B / 32; ++i) {      // 16 strips
            const int k4 = i * 32 + lane;
            ulonglong2 w0 = __ldcs(Wc0 + k4);
            ulonglong2 w1 = __ldcs(Wc1 + k4);
            ulonglong2 w2 = __ldcs(Wc2 + k4);
            ulonglong2 w3 = __ldcs(Wc3 + k4);

            #pragma unroll
            for (int b = 0; b < BATCH; b++) {
                ulonglong2 v = s_in[b * KS1_16B + k4];
                fma2(acc[0][b], w0.x, v.x);
                fma2(acc[0][b], w0.y, v.y);
                fma2(acc[1][b], w1.x, v.x);
                fma2(acc[1][b], w1.y, v.y);
                fma2(acc[2][b], w2.x, v.x);
                fma2(acc[2][b], w2.y, v.y);
                fma2(acc[3][b], w3.x, v.x);
                fma2(acc[3][b], w3.y, v.y);
            }
        }

        #pragma unroll
        for (int r = 0; r < R1; r++) {
            #pragma unroll
            for (int b = 0; b < BATCH; b++) {
                float s = pair_sum(acc[r][b]);
                #pragma unroll
                for (int off = 16; off > 0; off >>= 1)
                    s += __shfl_xor_sync(0xffffffffu, s, off);
                if (lane == b)
                    g_p1[slice][b][row0 + r] = s;
            }
        }
    }
}

// ===========================================================================
// Reduce 1: hidden = tanh(sum_8 p1 + bias1)   (float4)
// ===========================================================================
__global__ void rnn_reduce1_kernel(const float* __restrict__ bias)
{
    int idx = blockIdx.x * 256 + threadIdx.x;     // 16384 float4s
    int b  = idx >> 11;                            // / (HIDDEN/4)
    int h4 = idx & (HIDDEN_SIZE / 4 - 1);
    float4 a = __ldg((const float4*)bias + h4);
    #pragma unroll
    for (int s = 0; s < NSLICE1; s++) {
        float4 p = ((const float4*)&g_p1[s][b][0])[h4];
        a.x += p.x; a.y += p.y; a.z += p.z; a.w += p.w;
    }
    float4 r = make_float4(tanhf(a.x), tanhf(a.y), tanhf(a.z), tanhf(a.w));
    ((float4*)(g_hidden + b * HIDDEN_SIZE))[h4] = r;
}

// ===========================================================================
// Kernel 2: K-split GEMV (R13 proven). 16 rows/block, 2 halves, TK=1024.
// ===========================================================================
#define TK  1024
#define TK4 (TK / 4)
#define R2 2
#define ROWS_PER_BLOCK_2 (R2 * 8)   // 16
#define KSPLIT 2
#define KHALF (HIDDEN_SIZE / KSPLIT)   // 4096

__global__ __launch_bounds__(256, 2)
void rnn_h2o_kernel(const float* __restrict__ W2)   // [OUTPUT_SIZE, HIDDEN_SIZE]
{
    __shared__ float4 s_in[2][BATCH][TK4];   // 2 x 32 KB

    const int tid  = threadIdx.x;
    const int lane = tid & 31;
    const int warp = tid >> 5;
    const int tile = blockIdx.x & 127;
    const int half = blockIdx.x >> 7;
    const int row0 = tile * ROWS_PER_BLOCK_2 + warp * R2;
    const int kbase = half * KHALF;

    const int NCHUNK = KHALF / TK;   // 4

    float acc[R2][BATCH];
    #pragma unroll
    for (int r = 0; r < R2; r++)
        #pragma unroll
        for (int b = 0; b < BATCH; b++)
            acc[r][b] = 0.0f;

    auto stage = [&](int c, int buf) {
        const float* src = g_hidden + kbase + c * TK;
        #pragma unroll
        for (int t = 0; t < 8; ++t) {
            int f  = tid + t * 256;
            int b  = f >> 8;
            int k4 = f & (TK4 - 1);
            cp_async16(&s_in[buf][b][k4],
                       (const float4*)(src + (size_t)b * HIDDEN_SIZE) + k4);
        }
        cp_commit();
    };

    stage(0, 0);

    const float* W0 = W2 + (size_t)(row0 + 0) * HIDDEN_SIZE + kbase;
    const float* W1 = W2 + (size_t)(row0 + 1) * HIDDEN_SIZE + kbase;

    for (int c = 0; c < NCHUNK; ++c) {
        const int buf = c & 1;
        __syncthreads();
        if (c + 1 < NCHUNK) { stage(c + 1, buf ^ 1); cp_wait1(); }
        else                { cp_wait0(); }
        __syncthreads();

        const float* Wc0 = W0 + (size_t)c * TK;
        const float* Wc1 = W1 + (size_t)c * TK;

        #pragma unroll
        for (int i = 0; i < TK4 / 32; ++i) {
            const int k4 = i * 32 + lane;
            float4 w0 = __ldcs((const float4*)Wc0 + k4);
            float4 w1 = __ldcs((const float4*)Wc1 + k4);

            #pragma unroll
            for (int b = 0; b < BATCH; b++) {
                float4 v = s_in[buf][b][k4];
                acc[0][b] = fmaf(w0.x, v.x, acc[0][b]);
                acc[0][b] = fmaf(w0.y, v.y, acc[0][b]);
                acc[0][b] = fmaf(w0.z, v.z, acc[0][b]);
                acc[0][b] = fmaf(w0.w, v.w, acc[0][b]);
                acc[1][b] = fmaf(w1.x, v.x, acc[1][b]);
                acc[1][b] = fmaf(w1.y, v.y, acc[1][b]);
                acc[1][b] = fmaf(w1.z, v.z, acc[1][b]);
                acc[1][b] = fmaf(w1.w, v.w, acc[1][b]);
            }
        }
    }

    #pragma unroll
    for (int r = 0; r < R2; r++)
        #pragma unroll
        for (int b = 0; b < BATCH; b++)
            #pragma unroll
            for (int off = 16; off > 0; off >>= 1)
                acc[r][b] += __shfl_xor_sync(0xffffffffu, acc[r][b], off);

    #pragma unroll
    for (int r = 0; r < R2; r++) {
        const int row = row0 + r;
        #pragma unroll
        for (int b = 0; b < BATCH; b++)
            if (lane == b)
                g_part[half][b][row] = acc[r][b];
    }
}

// ===========================================================================
// Reduce 2: out = part[0] + part[1] + bias2
// ===========================================================================
__global__ void rnn_reduce_kernel(const float* __restrict__ bias2,
                                  float* __restrict__ out)
{
    int idx = blockIdx.x * blockDim.x + threadIdx.x;   // 16384
    int b = idx >> 11;
    int o = idx & (OUTPUT_SIZE - 1);
    out[idx] = g_part[0][b][o] + g_part[1][b][o] + __ldg(bias2 + o);
}

// ---------------------------------------------------------------------------
// Inputs: x, initial_hidden, i2h_weight, i2h_bias, h2o_weight, h2o_bias
// ---------------------------------------------------------------------------
extern "C" void kernel_launch(void* const* d_in, const int* in_sizes, int n_in,
                              void* d_out, int out_size) {
    const float* x  = (const float*)d_in[0];
    const float* h0 = (const float*)d_in[1];
    const float* W1 = (const float*)d_in[2];
    const float* b1 = (const float*)d_in[3];
    const float* W2 = (const float*)d_in[4];
    const float* b2 = (const float*)d_in[5];
    float* out      = (float*)d_out;

    const int SMEM1 = BATCH * KS1_16B * sizeof(ulonglong2);   // 64 KB dynamic
    cudaFuncSetAttribute(rnn_i2h_kernel,
                         cudaFuncAttributeMaxDynamicSharedMemorySize, SMEM1);

    rnn_i2h_kernel<<<NSLICE1 * BLKS_PER_SLICE1, 256, SMEM1>>>(x, h0, W1);
    rnn_reduce1_kernel<<<(BATCH * HIDDEN_SIZE / 4) / 256, 256>>>(b1);
    rnn_h2o_kernel<<<(OUTPUT_SIZE / ROWS_PER_BLOCK_2) * KSPLIT, 256>>>(W2);
    rnn_reduce_kernel<<<(BATCH * OUTPUT_SIZE) / 256, 256>>>(b2, out);
}

// round 15
// speedup vs baseline: 1.1750x; 1.0315x over previous
#include <cuda_runtime.h>

#define BATCH 8
#define INPUT_SIZE 8192
#define HIDDEN_SIZE 8192
#define OUTPUT_SIZE 2048
#define KDIM 16384

typedef unsigned long long u64;

// ---- Kernel 1: 8 K-slices x 37 persistent blocks = 296 = 2 x 148 SMs ------
#define NSLICE1 8
#define KSLICE1 (KDIM / NSLICE1)        // 2048
#define KS1_16B (KSLICE1 / 4)           // 512 x 16B per batch
#define BLKS_PER_SLICE1 37
#define R1 4
#define TILE_ROWS_1 (R1 * 8)            // 32
#define NTILES1 (HIDDEN_SIZE / TILE_ROWS_1)   // 256

// ---- Kernel 2: 64 row tiles x 4 K-splits = 256 blocks ---------------------
#define R2 4
#define TILE_ROWS_2 (R2 * 8)            // 32
#define NTILES2 (OUTPUT_SIZE / TILE_ROWS_2)   // 64
#define NSPLIT2 4
#define KQ (HIDDEN_SIZE / NSPLIT2)      // 2048

// Scratch (allocation-free)
__device__ float g_p1[NSLICE1][BATCH][HIDDEN_SIZE];   // 2 MB
__device__ float g_hidden[BATCH * HIDDEN_SIZE];       // 256 KB
__device__ float g_p2[NSPLIT2][BATCH][OUTPUT_SIZE];   // 256 KB

// ---------------------------------------------------------------------------
__device__ __forceinline__ void cp_async16(void* smem_dst, const void* gmem_src) {
    unsigned s = (unsigned)__cvta_generic_to_shared(smem_dst);
    asm volatile("cp.async.cg.shared.global [%0], [%1], 16;\n" :: "r"(s), "l"(gmem_src));
}
__device__ __forceinline__ void cp_commit()  { asm volatile("cp.async.commit_group;\n"); }
__device__ __forceinline__ void cp_wait1()   { asm volatile("cp.async.wait_group 1;\n"); }
__device__ __forceinline__ void cp_wait0()   { asm volatile("cp.async.wait_group 0;\n"); }

// Packed dual-FMA (non-volatile, reorderable). Operands are native
// ulonglong2 halves from LDG.128/LDS.128 — zero packing cost.
__device__ __forceinline__ void fma2(u64& d, u64 a, u64 b) {
    asm("fma.rn.f32x2 %0, %1, %2, %0;" : "+l"(d) : "l"(a), "l"(b));
}
__device__ __forceinline__ float pair_sum(u64 v) {
    return __uint_as_float((unsigned)v) + __uint_as_float((unsigned)(v >> 32));
}

// ===========================================================================
// Kernel 1: persistent slice-resident partial GEMV (FFMA2). UNCHANGED (R14).
// ===========================================================================
__global__ __launch_bounds__(256, 2)
void rnn_i2h_kernel(const float* __restrict__ x,
                    const float* __restrict__ h0,
                    const float* __restrict__ W)      // [HIDDEN_SIZE, KDIM]
{
    extern __shared__ ulonglong2 s_in[];              // [BATCH][KS1_16B] 64 KB

    const int tid   = threadIdx.x;
    const int lane  = tid & 31;
    const int warp  = tid >> 5;
    const int slice = blockIdx.x / BLKS_PER_SLICE1;   // 0..7
    const int local = blockIdx.x % BLKS_PER_SLICE1;   // 0..36

    const float* in = (slice < NSLICE1 / 2)
                        ? (x  + slice * KSLICE1)
                        : (h0 + slice * KSLICE1 - INPUT_SIZE);
    #pragma unroll
    for (int t = 0; t < 16; ++t) {
        int f  = tid + t * 256;
        int b  = f >> 9;                   // / KS1_16B (=512)
        int k4 = f & (KS1_16B - 1);
        s_in[b * KS1_16B + k4] =
            ((const ulonglong2*)(in + (size_t)b * INPUT_SIZE))[k4];
    }
    __syncthreads();        // the ONLY barrier

    const size_t koff = (size_t)slice * KSLICE1;

    for (int tile = local; tile < NTILES1; tile += BLKS_PER_SLICE1) {
        const int row0 = tile * TILE_ROWS_1 + warp * R1;

        u64 acc[R1][BATCH];
        #pragma unroll
        for (int r = 0; r < R1; r++)
            #pragma unroll
            for (int b = 0; b < BATCH; b++)
                acc[r][b] = 0ull;

        const ulonglong2* Wc0 = (const ulonglong2*)(W + (size_t)(row0 + 0) * KDIM + koff);
        const ulonglong2* Wc1 = (const ulonglong2*)(W + (size_t)(row0 + 1) * KDIM + koff);
        const ulonglong2* Wc2 = (const ulonglong2*)(W + (size_t)(row0 + 2) * KDIM + koff);
        const ulonglong2* Wc3 = (const ulonglong2*)(W + (size_t)(row0 + 3) * KDIM + koff);

        #pragma unroll
        for (int i = 0; i < KS1_16B / 32; ++i) {      // 16 strips
            const int k4 = i * 32 + lane;
            ulonglong2 w0 = __ldcs(Wc0 + k4);
            ulonglong2 w1 = __ldcs(Wc1 + k4);
            ulonglong2 w2 = __ldcs(Wc2 + k4);
            ulonglong2 w3 = __ldcs(Wc3 + k4);

            #pragma unroll
            for (int b = 0; b < BATCH; b++) {
                ulonglong2 v = s_in[b * KS1_16B + k4];
                fma2(acc[0][b], w0.x, v.x);
                fma2(acc[0][b], w0.y, v.y);
                fma2(acc[1][b], w1.x, v.x);
                fma2(acc[1][b], w1.y, v.y);
                fma2(acc[2][b], w2.x, v.x);
                fma2(acc[2][b], w2.y, v.y);
                fma2(acc[3][b], w3.x, v.x);
                fma2(acc[3][b], w3.y, v.y);
            }
        }

        #pragma unroll
        for (int r = 0; r < R1; r++) {
            #pragma unroll
            for (int b = 0; b < BATCH; b++) {
                float s = pair_sum(acc[r][b]);
                #pragma unroll
                for (int off = 16; off > 0; off >>= 1)
                    s += __shfl_xor_sync(0xffffffffu, s, off);
                if (lane == b)
                    g_p1[slice][b][row0 + r] = s;
            }
        }
    }
}

// ===========================================================================
// Reduce 1: hidden = tanh(sum_8 p1 + bias1)   (float4)
// ===========================================================================
__global__ void rnn_reduce1_kernel(const float* __restrict__ bias)
{
    int idx = blockIdx.x * 256 + threadIdx.x;     // 16384 float4s
    int b  = idx >> 11;                            // / (HIDDEN/4)
    int h4 = idx & (HIDDEN_SIZE / 4 - 1);
    float4 a = __ldg((const float4*)bias + h4);
    #pragma unroll
    for (int s = 0; s < NSLICE1; s++) {
        float4 p = ((const float4*)&g_p1[s][b][0])[h4];
        a.x += p.x; a.y += p.y; a.z += p.z; a.w += p.w;
    }
    float4 r = make_float4(tanhf(a.x), tanhf(a.y), tanhf(a.z), tanhf(a.w));
    ((float4*)(g_hidden + b * HIDDEN_SIZE))[h4] = r;
}

// ===========================================================================
// Kernel 2: h2o partial GEMV — kernel-1 shape: 4 rows/warp (halves LDS
// traffic vs 2 rows/warp), K-split x4 for grid=256, FFMA2 inner loop,
// TK=1024 double-buffered cp.async staging.
// ===========================================================================
#define TK  1024
#define TK16 (TK / 4)     // 256 x 16B per batch per chunk

__global__ __launch_bounds__(256, 2)
void rnn_h2o_kernel(const float* __restrict__ W2)   // [OUTPUT_SIZE, HIDDEN_SIZE]
{
    __shared__ ulonglong2 s_in[2][BATCH][TK16];   // 2 x 32 KB

    const int tid   = threadIdx.x;
    const int lane  = tid & 31;
    const int warp  = tid >> 5;
    const int tile  = blockIdx.x & (NTILES2 - 1);   // 0..63
    const int split = blockIdx.x >> 6;              // 0..3
    const int row0  = tile * TILE_ROWS_2 + warp * R2;
    const int kbase = split * KQ;

    const int NCHUNK = KQ / TK;   // 2

    u64 acc[R2][BATCH];
    #pragma unroll
    for (int r = 0; r < R2; r++)
        #pragma unroll
        for (int b = 0; b < BATCH; b++)
            acc[r][b] = 0ull;

    auto stage = [&](int c, int buf) {
        const float* src = g_hidden + kbase + c * TK;
        #pragma unroll
        for (int t = 0; t < 8; ++t) {
            int f  = tid + t * 256;
            int b  = f >> 8;               // / TK16 (=256)
            int k4 = f & (TK16 - 1);
            cp_async16(&s_in[buf][b][k4],
                       (const float4*)(src + (size_t)b * HIDDEN_SIZE) + k4);
        }
        cp_commit();
    };

    stage(0, 0);

    const ulonglong2* W0 = (const ulonglong2*)(W2 + (size_t)(row0 + 0) * HIDDEN_SIZE + kbase);
    const ulonglong2* W1 = (const ulonglong2*)(W2 + (size_t)(row0 + 1) * HIDDEN_SIZE + kbase);
    const ulonglong2* Wv2 = (const ulonglong2*)(W2 + (size_t)(row0 + 2) * HIDDEN_SIZE + kbase);
    const ulonglong2* W3 = (const ulonglong2*)(W2 + (size_t)(row0 + 3) * HIDDEN_SIZE + kbase);

    for (int c = 0; c < NCHUNK; ++c) {
        const int buf = c & 1;
        __syncthreads();
        if (c + 1 < NCHUNK) { stage(c + 1, buf ^ 1); cp_wait1(); }
        else                { cp_wait0(); }
        __syncthreads();

        const ulonglong2* Wc0 = W0 + c * TK16;
        const ulonglong2* Wc1 = W1 + c * TK16;
        const ulonglong2* Wc2 = Wv2 + c * TK16;
        const ulonglong2* Wc3 = W3 + c * TK16;

        #pragma unroll
        for (int i = 0; i < TK16 / 32; ++i) {         // 8 strips
            const int k4 = i * 32 + lane;
            ulonglong2 w0 = __ldcs(Wc0 + k4);
            ulonglong2 w1 = __ldcs(Wc1 + k4);
            ulonglong2 w2 = __ldcs(Wc2 + k4);
            ulonglong2 w3 = __ldcs(Wc3 + k4);

            #pragma unroll
            for (int b = 0; b < BATCH; b++) {
                ulonglong2 v = s_in[buf][b][k4];
                fma2(acc[0][b], w0.x, v.x);
                fma2(acc[0][b], w0.y, v.y);
                fma2(acc[1][b], w1.x, v.x);
                fma2(acc[1][b], w1.y, v.y);
                fma2(acc[2][b], w2.x, v.x);
                fma2(acc[2][b], w2.y, v.y);
                fma2(acc[3][b], w3.x, v.x);
                fma2(acc[3][b], w3.y, v.y);
            }
        }
    }

    #pragma unroll
    for (int r = 0; r < R2; r++) {
        #pragma unroll
        for (int b = 0; b < BATCH; b++) {
            float s = pair_sum(acc[r][b]);
            #pragma unroll
            for (int off = 16; off > 0; off >>= 1)
                s += __shfl_xor_sync(0xffffffffu, s, off);
            if (lane == b)
                g_p2[split][b][row0 + r] = s;
        }
    }
}

// ===========================================================================
// Reduce 2: out = sum_4 p2 + bias2   (float4)
// ===========================================================================
__global__ void rnn_reduce2_kernel(const float* __restrict__ bias2,
                                   float* __restrict__ out)
{
    int idx = blockIdx.x * 256 + threadIdx.x;     // 4096 float4s
    int b  = idx >> 9;                             // / (OUT/4)
    int o4 = idx & (OUTPUT_SIZE / 4 - 1);
    float4 a = __ldg((const float4*)bias2 + o4);
    #pragma unroll
    for (int s = 0; s < NSPLIT2; s++) {
        float4 p = ((const float4*)&g_p2[s][b][0])[o4];
        a.x += p.x; a.y += p.y; a.z += p.z; a.w += p.w;
    }
    ((float4*)out)[idx] = a;
}

// ---------------------------------------------------------------------------
// Inputs: x, initial_hidden, i2h_weight, i2h_bias, h2o_weight, h2o_bias
// ---------------------------------------------------------------------------
extern "C" void kernel_launch(void* const* d_in, const int* in_sizes, int n_in,
                              void* d_out, int out_size) {
    const float* x  = (const float*)d_in[0];
    const float* h0 = (const float*)d_in[1];
    const float* W1 = (const float*)d_in[2];
    const float* b1 = (const float*)d_in[3];
    const float* W2 = (const float*)d_in[4];
    const float* b2 = (const float*)d_in[5];
    float* out      = (float*)d_out;

    const int SMEM1 = BATCH * KS1_16B * sizeof(ulonglong2);   // 64 KB dynamic
    cudaFuncSetAttribute(rnn_i2h_kernel,
                         cudaFuncAttributeMaxDynamicSharedMemorySize, SMEM1);

    rnn_i2h_kernel<<<NSLICE1 * BLKS_PER_SLICE1, 256, SMEM1>>>(x, h0, W1);
    rnn_reduce1_kernel<<<(BATCH * HIDDEN_SIZE / 4) / 256, 256>>>(b1);
    rnn_h2o_kernel<<<NTILES2 * NSPLIT2, 256>>>(W2);
    rnn_reduce2_kernel<<<(BATCH * OUTPUT_SIZE / 4) / 256, 256>>>(b2, out);
}